// round 12
// baseline (speedup 1.0000x reference)
#include <cuda_runtime.h>
#include <cuda_fp16.h>
#include <cstdint>

// ============================================================================
// MotherCubeConv: y[n] = concat(x[n], x[nbr0..3(n)]) @ W^T + b
//   N=200000, F_in=128, fan_in=640, F_out=128.
// fp16 mma.sync. R12: CTA 256x128 (512 thr), warp tile 32x64 (8m x 2n grid):
// 16 HMMA per 6 LDSM (was 8) -> more tensor work per fragment batch, fewer
// fragment bytes/MAC. W+A both streamed double-buffered, one barrier/slot,
// persistent CTAs. Bias read from smem in epilogue (saves 16 regs, no spill).
// ============================================================================

#define NSLOT 5
#define MAX_ROWS 200704

// ---- scratch (__device__ globals; no allocation allowed) -------------------
__device__ uint4 g_Wh[NSLOT * 2048];            // 5 x [128x128] fp16, swizzled
__device__ uint4 g_x16[(size_t)MAX_ROWS * 16];  // fp16 image of x (51.4MB)
__device__ int   g_is64;

// ---- helpers ----------------------------------------------------------------
__device__ __forceinline__ uint32_t smem_u32(const void* p) {
    uint32_t a;
    asm("{ .reg .u64 t; cvta.to.shared.u64 t, %1; cvt.u32.u64 %0, t; }"
        : "=r"(a) : "l"(p));
    return a;
}

__device__ __forceinline__ void ldsm_x4(uint32_t* r, uint32_t addr) {
    asm volatile("ldmatrix.sync.aligned.m8n8.x4.shared.b16 {%0,%1,%2,%3}, [%4];"
                 : "=r"(r[0]), "=r"(r[1]), "=r"(r[2]), "=r"(r[3]) : "r"(addr));
}

__device__ __forceinline__ void mma16816(float* d, const uint32_t* a,
                                         const uint32_t* b) {
    asm volatile(
        "mma.sync.aligned.m16n8k16.row.col.f32.f16.f16.f32 "
        "{%0,%1,%2,%3}, {%4,%5,%6,%7}, {%8,%9}, {%0,%1,%2,%3};"
        : "+f"(d[0]), "+f"(d[1]), "+f"(d[2]), "+f"(d[3])
        : "r"(a[0]), "r"(a[1]), "r"(a[2]), "r"(a[3]), "r"(b[0]), "r"(b[1]));
}

#define CP_ASYNC16(dst, src) \
    asm volatile("cp.async.cg.shared.global [%0], [%1], 16;" \
                 :: "r"(dst), "l"(src) : "memory")
#define CP_COMMIT() asm volatile("cp.async.commit_group;" ::: "memory")

// Swizzled byte offset: 256B row stride (16 groups of 16B), group XOR row&7.
__device__ __host__ __forceinline__ uint32_t tile_off(int row, int k) {
    uint32_t g = (uint32_t)(k >> 3);
    return (uint32_t)row * 256u + (((g ^ (uint32_t)(row & 7)) << 4)) +
           (uint32_t)(k & 7) * 2u;
}

// ---- fused prologue: cvt x -> fp16 image, W -> fp16 swizzled, dtype detect --
__global__ void prep_kernel(const float* __restrict__ x,
                            const float* __restrict__ W,
                            const int* __restrict__ nbr, int ngroups) {
    const int t = blockIdx.x * blockDim.x + threadIdx.x;
    if (t < ngroups) {
        const float4* s = (const float4*)x + (size_t)t * 2;
        float4 a = s[0], b = s[1];
        __half2 h0 = __floats2half2_rn(a.x, a.y);
        __half2 h1 = __floats2half2_rn(a.z, a.w);
        __half2 h2 = __floats2half2_rn(b.x, b.y);
        __half2 h3 = __floats2half2_rn(b.z, b.w);
        uint4 u;
        u.x = *(uint32_t*)&h0; u.y = *(uint32_t*)&h1;
        u.z = *(uint32_t*)&h2; u.w = *(uint32_t*)&h3;
        g_x16[t] = u;
    }
    if (t < NSLOT * 128 * 64) {
        int cp = t & 63;
        int f  = (t >> 6) & 127;
        int j  = t >> 13;
        int k  = cp * 2;
        __half2 h = __floats2half2_rn(W[f * 640 + j * 128 + k],
                                      W[f * 640 + j * 128 + k + 1]);
        *(uint32_t*)((char*)g_Wh + (size_t)j * 32768 + tile_off(f, k)) =
            *(uint32_t*)&h;
    }
    if (t == 0) {
        int all0 = 1;
        for (int i = 0; i < 64; i++)
            if (nbr[2 * i + 1] != 0) { all0 = 0; break; }
        g_is64 = all0;
    }
}

// ---- SMEM layout --------------------------------------------------------------
static constexpr uint32_t OFF_BIAS = 0;        // 512B
static constexpr uint32_t OFF_W    = 1024;     // 2 x 32KB (streamed)
static constexpr uint32_t OFF_A    = 66560;    // 2 x 64KB (256-row tiles)
static constexpr uint32_t SMEM_BYTES = 197632;

__global__ void __launch_bounds__(512, 1)
mcconv_kernel(const void* __restrict__ nbr_raw,
              const float* __restrict__ bias_g, float* __restrict__ out, int N) {
    extern __shared__ char smem[];
    const uint32_t sb = smem_u32(smem);
    const int tid = threadIdx.x;
    const int wid = tid >> 5;
    const int lid = tid & 31;
    const int ntiles = (N + 255) >> 8;

    if (tid < 128) ((float*)(smem + OFF_BIAS))[tid] = bias_g[tid];

    const int r    = tid >> 1;            // tile row 0..255 this thread stages
    const int c0   = (tid & 1) * 8;       // first of 8 16B-chunks (of 16)
    const int is64 = g_is64;
    const long long* nbr64 = (const long long*)nbr_raw;
    const int*       nbr32 = (const int*)nbr_raw;

    auto load_idxs = [&](int tile, int* dst) {
        const int grow = tile * 256 + r;
        const bool v = grow < N;
        const int base = v ? grow : 0;
        dst[0] = base;
        if (is64) {
            const long long* p = nbr64 + (size_t)base * 4;
            #pragma unroll
            for (int k = 0; k < 4; ++k) dst[k + 1] = v ? (int)p[k] : 0;
        } else {
            const int* p = nbr32 + (size_t)base * 4;
            #pragma unroll
            for (int k = 0; k < 4; ++k) dst[k + 1] = v ? p[k] : 0;
        }
    };

    // stage W slot j into buffer buf (32KB flat copy of pre-swizzled image)
    auto stage_W = [&](int j, int buf) {
        const char* src = (const char*)g_Wh + (size_t)j * 32768;
        const uint32_t dst = sb + OFF_W + (uint32_t)buf * 32768u;
        #pragma unroll
        for (int w = 0; w < 4; ++w) {
            const uint32_t e = (uint32_t)(tid + w * 512) * 16u;
            CP_ASYNC16(dst + e, src + e);
        }
    };
    // stage A slot j into buffer buf (64KB gather, swizzled dst)
    auto stage_A = [&](int src_row, int buf) {
        const char* src = (const char*)g_x16 + (size_t)src_row * 256;
        const uint32_t dst = sb + OFF_A + (uint32_t)buf * 65536u;
        #pragma unroll
        for (int c = 0; c < 8; ++c) {
            const int chunk = c0 + c;
            CP_ASYNC16(dst + tile_off(r, chunk * 8), src + chunk * 16);
        }
    };

    int idxs[NSLOT], nidxs[NSLOT];
    int tile = blockIdx.x;
    if (tile < ntiles) {
        load_idxs(tile, idxs);
        stage_W(0, 0);
        stage_A(idxs[0], 0);
    }
    CP_COMMIT();   // group: slot 0

    // warp tiling: 8 (M) x 2 (N); warp tile = 32 rows x 64 cols
    const int wm = wid >> 1;
    const int wn = wid & 1;

    float acc[2][8][4];   // [mt][nt][reg]
    #pragma unroll
    for (int mt = 0; mt < 2; ++mt)
        #pragma unroll
        for (int nt = 0; nt < 8; ++nt)
            #pragma unroll
            for (int q = 0; q < 4; ++q) acc[mt][nt][q] = 0.0f;

    const int a_row  = (lid & 15);
    const int a_gsel = (lid >> 4);
    const int b_row  = (lid & 7);
    const int b_ntin = (lid >> 4);        // which nt within a pair
    const int b_gsel = ((lid >> 3) & 1);  // k-group select

    const int rl = lid >> 2;
    const int cl = (lid & 3) * 2;

    int buf = 0;
    for (; tile < ntiles; tile += gridDim.x) {
        const int next_tile = tile + (int)gridDim.x;
        #pragma unroll
        for (int j = 0; j < NSLOT; ++j) {
            if (j == 3 && next_tile < ntiles) load_idxs(next_tile, nidxs);

            asm volatile("cp.async.wait_group 0;" ::: "memory");  // slot j landed
            __syncthreads();   // all warps done with buf^1; W/A[buf] visible

            // stage next slot into buf^1 — overlaps this slot's MMA phase
            const bool has_next = (j < NSLOT - 1) || (next_tile < ntiles);
            if (has_next) {
                const int nj = (j < NSLOT - 1) ? j + 1 : 0;
                const int src_row = (j < NSLOT - 1) ? idxs[j + 1] : nidxs[0];
                stage_W(nj, buf ^ 1);
                stage_A(src_row, buf ^ 1);
                CP_COMMIT();
            }

            const uint32_t wbase = sb + OFF_W + (uint32_t)buf * 32768u;
            const uint32_t abase = sb + OFF_A + (uint32_t)buf * 65536u;
            #pragma unroll
            for (int kc = 0; kc < 8; ++kc) {
                // B frags: 4 x4 loads cover nt pairs {0,1}..{6,7}
                uint32_t bh[8][2];
                const int gB = kc * 2 + b_gsel;
                #pragma unroll
                for (int p = 0; p < 4; ++p) {
                    const int nr = wn * 64 + p * 16 + b_ntin * 8 + b_row;
                    const uint32_t off =
                        (uint32_t)nr * 256u + (((uint32_t)(gB ^ (nr & 7))) << 4);
                    uint32_t rr[4];
                    ldsm_x4(rr, wbase + off);
                    bh[p * 2 + 0][0] = rr[0];
                    bh[p * 2 + 0][1] = rr[1];
                    bh[p * 2 + 1][0] = rr[2];
                    bh[p * 2 + 1][1] = rr[3];
                }
                // A frags: one x4 per mt (2 m-tiles of 16 rows)
                const int gA = kc * 2 + a_gsel;
                #pragma unroll
                for (int mt = 0; mt < 2; ++mt) {
                    const int ar = wm * 32 + mt * 16 + a_row;
                    const uint32_t off =
                        (uint32_t)ar * 256u + (((uint32_t)(gA ^ (ar & 7))) << 4);
                    uint32_t ah[4];
                    ldsm_x4(ah, abase + off);
                    #pragma unroll
                    for (int nt = 0; nt < 8; ++nt)
                        mma16816(acc[mt][nt], ah, bh[nt]);
                }
            }
            buf ^= 1;
        }

        // ---- epilogue (bias from smem; overlaps next tile's slot-0 staging) ----
        const int row0 = tile * 256;
        const float* bs = (const float*)(smem + OFF_BIAS);
        #pragma unroll
        for (int mt = 0; mt < 2; ++mt) {
            const int r_base = row0 + wm * 32 + mt * 16 + rl;
            #pragma unroll
            for (int nt = 0; nt < 8; ++nt) {
                const int col = wn * 64 + nt * 8 + cl;
                const float b0 = bs[col], b1 = bs[col + 1];
                if (r_base < N) {
                    float2 vv = make_float2(acc[mt][nt][0] + b0,
                                            acc[mt][nt][1] + b1);
                    *(float2*)(out + (size_t)r_base * 128 + col) = vv;
                }
                if (r_base + 8 < N) {
                    float2 vv = make_float2(acc[mt][nt][2] + b0,
                                            acc[mt][nt][3] + b1);
                    *(float2*)(out + (size_t)(r_base + 8) * 128 + col) = vv;
                }
                #pragma unroll
                for (int q = 0; q < 4; ++q) acc[mt][nt][q] = 0.0f;
            }
        }

        #pragma unroll
        for (int k = 0; k < NSLOT; ++k) idxs[k] = nidxs[k];
    }
}

// ---- launch ------------------------------------------------------------------
extern "C" void kernel_launch(void* const* d_in, const int* in_sizes, int n_in,
                              void* d_out, int out_size) {
    const float* x   = (const float*)d_in[0];
    const void*  nbr = d_in[1];
    const float* W   = (const float*)d_in[2];
    const float* b   = (const float*)d_in[3];
    float* out = (float*)d_out;
    const int N = in_sizes[0] / 128;
    const int ngroups = N * 16;   // 8 fp32 elems per group

    cudaFuncSetAttribute(mcconv_kernel,
                         cudaFuncAttributeMaxDynamicSharedMemorySize, SMEM_BYTES);

    prep_kernel<<<(ngroups + 255) / 256, 256>>>(x, W, (const int*)nbr, ngroups);
    mcconv_kernel<<<148, 512, SMEM_BYTES>>>(nbr, b, out, N);
}

// round 13
// speedup vs baseline: 1.3964x; 1.3964x over previous
#include <cuda_runtime.h>
#include <cuda_fp16.h>
#include <cstdint>

// ============================================================================
// MotherCubeConv: y[n] = concat(x[n], x[nbr0..3(n)]) @ W^T + b
//   N=200000, F_in=128, fan_in=640, F_out=128.
// fp16 mma.sync. R13 = R10 (best) + B fragments via ldmatrix.x4 (6->4 LDSM
// per kc) + bias kept in smem (register slack; R10 sat at the 128-reg cap).
// Persistent CTAs, one barrier per slot, W resident (160KB staged once),
// A double-buffered cp.async from prebuilt fp16 image of x.
// ============================================================================

#define NSLOT 5
#define MAX_ROWS 200704

// ---- scratch (__device__ globals; no allocation allowed) -------------------
__device__ uint4 g_Wh[NSLOT * 2048];            // 5 x [128x128] fp16, swizzled
__device__ uint4 g_x16[(size_t)MAX_ROWS * 16];  // fp16 image of x (51.4MB)
__device__ int   g_is64;

// ---- helpers ----------------------------------------------------------------
__device__ __forceinline__ uint32_t smem_u32(const void* p) {
    uint32_t a;
    asm("{ .reg .u64 t; cvta.to.shared.u64 t, %1; cvt.u32.u64 %0, t; }"
        : "=r"(a) : "l"(p));
    return a;
}

__device__ __forceinline__ void ldsm_x4(uint32_t* r, uint32_t addr) {
    asm volatile("ldmatrix.sync.aligned.m8n8.x4.shared.b16 {%0,%1,%2,%3}, [%4];"
                 : "=r"(r[0]), "=r"(r[1]), "=r"(r[2]), "=r"(r[3]) : "r"(addr));
}

__device__ __forceinline__ void mma16816(float* d, const uint32_t* a,
                                         const uint32_t* b) {
    asm volatile(
        "mma.sync.aligned.m16n8k16.row.col.f32.f16.f16.f32 "
        "{%0,%1,%2,%3}, {%4,%5,%6,%7}, {%8,%9}, {%0,%1,%2,%3};"
        : "+f"(d[0]), "+f"(d[1]), "+f"(d[2]), "+f"(d[3])
        : "r"(a[0]), "r"(a[1]), "r"(a[2]), "r"(a[3]), "r"(b[0]), "r"(b[1]));
}

#define CP_ASYNC16(dst, src) \
    asm volatile("cp.async.cg.shared.global [%0], [%1], 16;" \
                 :: "r"(dst), "l"(src) : "memory")
#define CP_COMMIT() asm volatile("cp.async.commit_group;" ::: "memory")

// Swizzled byte offset: 256B row stride (16 groups of 16B), group XOR row&7.
__device__ __host__ __forceinline__ uint32_t tile_off(int row, int k) {
    uint32_t g = (uint32_t)(k >> 3);
    return (uint32_t)row * 256u + (((g ^ (uint32_t)(row & 7)) << 4)) +
           (uint32_t)(k & 7) * 2u;
}

// ---- fused prologue: cvt x -> fp16 image, W -> fp16 swizzled, dtype detect --
__global__ void prep_kernel(const float* __restrict__ x,
                            const float* __restrict__ W,
                            const int* __restrict__ nbr, int ngroups) {
    const int t = blockIdx.x * blockDim.x + threadIdx.x;
    if (t < ngroups) {
        const float4* s = (const float4*)x + (size_t)t * 2;
        float4 a = s[0], b = s[1];
        __half2 h0 = __floats2half2_rn(a.x, a.y);
        __half2 h1 = __floats2half2_rn(a.z, a.w);
        __half2 h2 = __floats2half2_rn(b.x, b.y);
        __half2 h3 = __floats2half2_rn(b.z, b.w);
        uint4 u;
        u.x = *(uint32_t*)&h0; u.y = *(uint32_t*)&h1;
        u.z = *(uint32_t*)&h2; u.w = *(uint32_t*)&h3;
        g_x16[t] = u;
    }
    if (t < NSLOT * 128 * 64) {
        int cp = t & 63;
        int f  = (t >> 6) & 127;
        int j  = t >> 13;
        int k  = cp * 2;
        __half2 h = __floats2half2_rn(W[f * 640 + j * 128 + k],
                                      W[f * 640 + j * 128 + k + 1]);
        *(uint32_t*)((char*)g_Wh + (size_t)j * 32768 + tile_off(f, k)) =
            *(uint32_t*)&h;
    }
    if (t == 0) {
        int all0 = 1;
        for (int i = 0; i < 64; i++)
            if (nbr[2 * i + 1] != 0) { all0 = 0; break; }
        g_is64 = all0;
    }
}

// ---- SMEM layout --------------------------------------------------------------
static constexpr uint32_t OFF_BIAS = 0;        // 512B
static constexpr uint32_t OFF_W    = 1024;     // 5 x 32KB (resident)
static constexpr uint32_t OFF_A    = 164864;   // 2 x 32KB
static constexpr uint32_t SMEM_BYTES = 230400;

__global__ void __launch_bounds__(512, 1)
mcconv_kernel(const void* __restrict__ nbr_raw,
              const float* __restrict__ bias_g, float* __restrict__ out, int N) {
    extern __shared__ char smem[];
    const uint32_t sb = smem_u32(smem);
    const int tid = threadIdx.x;
    const int wid = tid >> 5;
    const int lid = tid & 31;
    const int ntiles = (N + 127) >> 7;

    if (tid < 128) ((float*)(smem + OFF_BIAS))[tid] = bias_g[tid];

    // ---- stage all W (160KB) once ---------------------------------------------
    {
        const char* src = (const char*)g_Wh;
        const uint32_t dst = sb + OFF_W;
        #pragma unroll
        for (int w = 0; w < 20; ++w) {
            const uint32_t e = (uint32_t)(tid + w * 512) * 16u;
            CP_ASYNC16(dst + e, src + e);
        }
    }

    const int r    = tid >> 2;            // tile row 0..127 this thread stages
    const int c0   = (tid & 3) * 4;       // first of 4 16B-chunks (of 16)
    const int is64 = g_is64;
    const long long* nbr64 = (const long long*)nbr_raw;
    const int*       nbr32 = (const int*)nbr_raw;

    auto load_idxs = [&](int tile, int* dst) {
        const int grow = tile * 128 + r;
        const bool v = grow < N;
        const int base = v ? grow : 0;
        dst[0] = base;
        if (is64) {
            const long long* p = nbr64 + (size_t)base * 4;
            #pragma unroll
            for (int k = 0; k < 4; ++k) dst[k + 1] = v ? (int)p[k] : 0;
        } else {
            const int* p = nbr32 + (size_t)base * 4;
            #pragma unroll
            for (int k = 0; k < 4; ++k) dst[k + 1] = v ? p[k] : 0;
        }
    };

    auto stage_A = [&](int src_row, int buf) {
        const char* src = (const char*)g_x16 + (size_t)src_row * 256;
        const uint32_t dst = sb + OFF_A + (uint32_t)buf * 32768u;
        #pragma unroll
        for (int c = 0; c < 4; ++c) {
            const int chunk = c0 + c;
            CP_ASYNC16(dst + tile_off(r, chunk * 8), src + chunk * 16);
        }
    };

    int idxs[NSLOT], nidxs[NSLOT];
    int tile = blockIdx.x;
    if (tile < ntiles) {
        load_idxs(tile, idxs);
        stage_A(idxs[0], 0);
    }
    CP_COMMIT();   // group: W + A(tile0, slot0)

    // warp tiling: 4 (M) x 4 (N); warp tile = 32 rows x 32 cols
    const int wm = wid >> 2;
    const int wn = wid & 3;

    float acc[2][4][4];
    #pragma unroll
    for (int mt = 0; mt < 2; ++mt)
        #pragma unroll
        for (int nt = 0; nt < 4; ++nt)
            #pragma unroll
            for (int q = 0; q < 4; ++q) acc[mt][nt][q] = 0.0f;

    const int a_row  = (lid & 15);
    const int a_gsel = (lid >> 4);
    const int b_row  = (lid & 7);
    const int b_ntin = (lid >> 4);        // which nt within a pair
    const int b_gsel = ((lid >> 3) & 1);  // k-group select

    const int rl = lid >> 2;
    const int cl = (lid & 3) * 2;

    int buf = 0;
    for (; tile < ntiles; tile += gridDim.x) {
        const int next_tile = tile + (int)gridDim.x;
        #pragma unroll
        for (int j = 0; j < NSLOT; ++j) {
            // prefetch next tile's indices mid-stream
            if (j == 3 && next_tile < ntiles) load_idxs(next_tile, nidxs);

            asm volatile("cp.async.wait_group 0;" ::: "memory");  // A_j landed
            __syncthreads();   // all warps done with buf^1; A[buf] visible

            // stage next slot into buf^1 — overlaps this slot's MMA phase
            const bool has_next = (j < NSLOT - 1) || (next_tile < ntiles);
            if (has_next) {
                const int src_row = (j < NSLOT - 1) ? idxs[j + 1] : nidxs[0];
                stage_A(src_row, buf ^ 1);
                CP_COMMIT();
            }

            const uint32_t wbase = sb + OFF_W + (uint32_t)j * 32768u;
            const uint32_t abase = sb + OFF_A + (uint32_t)buf * 32768u;
            #pragma unroll
            for (int kc = 0; kc < 8; ++kc) {
                // B frags: two x4 loads cover nt pairs {0,1},{2,3}
                uint32_t bh[4][2];
                const int gB = kc * 2 + b_gsel;
                #pragma unroll
                for (int p = 0; p < 2; ++p) {
                    const int nr = wn * 32 + p * 16 + b_ntin * 8 + b_row;
                    const uint32_t off =
                        (uint32_t)nr * 256u + (((uint32_t)(gB ^ (nr & 7))) << 4);
                    uint32_t rr[4];
                    ldsm_x4(rr, wbase + off);
                    bh[p * 2 + 0][0] = rr[0];
                    bh[p * 2 + 0][1] = rr[1];
                    bh[p * 2 + 1][0] = rr[2];
                    bh[p * 2 + 1][1] = rr[3];
                }
                // A frags: one x4 per mt (2 m-tiles of 16 rows)
                const int gA = kc * 2 + a_gsel;
                #pragma unroll
                for (int mt = 0; mt < 2; ++mt) {
                    const int ar = wm * 32 + mt * 16 + a_row;
                    const uint32_t off =
                        (uint32_t)ar * 256u + (((uint32_t)(gA ^ (ar & 7))) << 4);
                    uint32_t ah[4];
                    ldsm_x4(ah, abase + off);
                    #pragma unroll
                    for (int nt = 0; nt < 4; ++nt)
                        mma16816(acc[mt][nt], ah, bh[nt]);
                }
            }
            buf ^= 1;
        }

        // ---- epilogue (bias from smem; overlaps next tile's slot-0 staging) ----
        const int row0 = tile * 128;
        const float* bs = (const float*)(smem + OFF_BIAS);
        #pragma unroll
        for (int mt = 0; mt < 2; ++mt) {
            const int r_base = row0 + wm * 32 + mt * 16 + rl;
            #pragma unroll
            for (int nt = 0; nt < 4; ++nt) {
                const int col = wn * 32 + nt * 8 + cl;
                const float b0 = bs[col], b1 = bs[col + 1];
                if (r_base < N) {
                    float2 vv = make_float2(acc[mt][nt][0] + b0,
                                            acc[mt][nt][1] + b1);
                    *(float2*)(out + (size_t)r_base * 128 + col) = vv;
                }
                if (r_base + 8 < N) {
                    float2 vv = make_float2(acc[mt][nt][2] + b0,
                                            acc[mt][nt][3] + b1);
                    *(float2*)(out + (size_t)(r_base + 8) * 128 + col) = vv;
                }
                #pragma unroll
                for (int q = 0; q < 4; ++q) acc[mt][nt][q] = 0.0f;
            }
        }

        // roll prefetched indices
        #pragma unroll
        for (int k = 0; k < NSLOT; ++k) idxs[k] = nidxs[k];
    }
}

// ---- launch ------------------------------------------------------------------
extern "C" void kernel_launch(void* const* d_in, const int* in_sizes, int n_in,
                              void* d_out, int out_size) {
    const float* x   = (const float*)d_in[0];
    const void*  nbr = d_in[1];
    const float* W   = (const float*)d_in[2];
    const float* b   = (const float*)d_in[3];
    float* out = (float*)d_out;
    const int N = in_sizes[0] / 128;
    const int ngroups = N * 16;   // 8 fp32 elems per group

    cudaFuncSetAttribute(mcconv_kernel,
                         cudaFuncAttributeMaxDynamicSharedMemorySize, SMEM_BYTES);

    prep_kernel<<<(ngroups + 255) / 256, 256>>>(x, W, (const int*)nbr, ngroups);
    mcconv_kernel<<<148, 512, SMEM_BYTES>>>(nbr, b, out, N);
}